// round 16
// baseline (speedup 1.0000x reference)
#include <cuda_runtime.h>
#include <cstdint>

// ---------------- problem constants ----------------
#define DE_V   19000
#define EMB_E  64
#define HID    32
#define G4     128
#define BB     64
#define S_EN   50
#define S_DE   50
#define NSTEP  (S_DE - 1)

// persistent grid config
#define NBLK    148
#define GROUPS  4
#define CHUNKS  37
#define BPG     16
#define RPC     514          // 37*514 = 19018 >= 19000
#define NT      512          // threads per block (16 warps)

// phase-A block ranges
#define NEBLK   38           // blocks 0..37: E precompute (38*512 >= 19000)
#define ENCBLK0 38           // blocks 38..101: encoder (tid<128)
#define ZBLK0   102          // blocks 102..147: zeroing

// ---------------- dynamic smem layout ----------------
#define WHH_OFF   0          // u64[16][128] transposed Whh pairs = 16384
#define RED_OFF   16384      // u64[16][512] packed argmax        = 65536
#define HP_OFF    81920      // float[16][32]                     = 2048
#define HN_OFF    83968      // float[16][32]                     = 2048
#define GS_OFF    86016      // float[16][128]                    = 8192
#define TOK_OFF   94208      // int[16] (+pad)                    = 128
#define SMEM_TOTAL 94336
// phase-A aliases
#define WS_OFF    0          // E-blocks: dec_Wih [128*32]f
#define BIAS_OFF  16384      // E-blocks: bias[128]
#define ENC_OFF   16384      // encoder blocks: scratch

typedef unsigned long long u64;

// ---------------- device scratch ----------------
__device__ float g_h[2][BB][HID];
__device__ float g_c[2][BB][HID];
__device__ float g_E[DE_V][G4];
__device__ u64   g_amax[NSTEP][BB];
__device__ unsigned          g_bar_count;
__device__ volatile unsigned g_bar_gen;
__device__ unsigned g_done[GROUPS][64];

// ---------------- helpers ----------------
__device__ __forceinline__ float sigf(float x) { return 1.0f / (1.0f + expf(-x)); }
__device__ __forceinline__ float tanh_acc(float x) {
    float ax = fabsf(x);
    float e  = expf(-2.0f * ax);
    float r  = (1.0f - e) / (1.0f + e);
    return (x < 0.0f) ? -r : r;
}
__device__ __forceinline__ u64 fma2(u64 a, u64 b, u64 c) {
    u64 d;
    asm("fma.rn.f32x2 %0, %1, %2, %3;" : "=l"(d) : "l"(a), "l"(b), "l"(c));
    return d;
}
__device__ __forceinline__ float lo32(u64 v) { return __uint_as_float((unsigned)v); }
__device__ __forceinline__ float hi32(u64 v) { return __uint_as_float((unsigned)(v >> 32)); }
__device__ __forceinline__ unsigned key_of(float f) {
    unsigned u = __float_as_uint(f);
    return (u & 0x80000000u) ? ~u : (u | 0x80000000u);
}
__device__ __forceinline__ void bar_enc() {
    asm volatile("bar.sync 1, 128;" ::: "memory");
}

__device__ __forceinline__ void grid_sync() {
    __syncthreads();
    if (threadIdx.x == 0) {
        unsigned gen = g_bar_gen;
        __threadfence();
        unsigned prev = atomicAdd(&g_bar_count, 1u);
        if (prev == gridDim.x - 1) {
            atomicExch(&g_bar_count, 0u);
            __threadfence();
            g_bar_gen = gen + 1;
        } else {
            while (g_bar_gen == gen) { }
            __threadfence();
        }
    }
    __syncthreads();
}

// ---------------- the persistent kernel ----------------
__global__ void __launch_bounds__(NT, 1) seq2seq_kernel(
    const int*   __restrict__ en_batch,
    const int*   __restrict__ en_lens,
    const int*   __restrict__ de_batch,
    const float* __restrict__ en_emb,
    const float* __restrict__ enc_Wih,
    const float* __restrict__ enc_Whh,
    const float* __restrict__ enc_bih,
    const float* __restrict__ enc_bhh,
    const float* __restrict__ de_emb,
    const float* __restrict__ dec_Wih,
    const float* __restrict__ dec_bih,
    const float* __restrict__ dec_bhh,
    const float* __restrict__ dec_Whh,
    const float* __restrict__ fc_W,
    const float* __restrict__ fc_b,
    float*       __restrict__ out)
{
    extern __shared__ __align__(16) unsigned char sdyn[];
    const int blk = blockIdx.x;
    const int tid = threadIdx.x;

    // ================= PHASE A =================
    if (blk < NEBLK) {
        // ---- E = de_emb @ dec_Wih.T + bih + bhh : one vocab row per thread ----
        float* Ws    = (float*)(sdyn + WS_OFF);
        float* biasS = (float*)(sdyn + BIAS_OFF);
        for (int i = tid; i < G4 * HID; i += NT) Ws[i] = dec_Wih[i];
        if (tid < G4) biasS[tid] = dec_bih[tid] + dec_bhh[tid];
        __syncthreads();
        int v = blk * NT + tid;
        if (v < DE_V) {
            const u64* xr = (const u64*)(de_emb + (size_t)v * HID);
            u64 x2[16];
#pragma unroll
            for (int k = 0; k < 16; k++) x2[k] = xr[k];
            const u64* W2 = (const u64*)Ws;
            float* Erow = &g_E[v][0];
            for (int g = 0; g < G4; g += 4) {
                float4 r;
                float* rp = (float*)&r;
#pragma unroll
                for (int gg = 0; gg < 4; gg++) {
                    u64 acc = 0ull;
                    const u64* w = W2 + (size_t)(g + gg) * 16;
#pragma unroll
                    for (int k = 0; k < 16; k++) acc = fma2(w[k], x2[k], acc);
                    rp[gg] = lo32(acc) + hi32(acc) + biasS[g + gg];
                }
                *(float4*)(Erow + g) = r;
            }
        }
    } else if (blk < ZBLK0) {
        if (tid < 128) {
            // ---- encoder: one batch element per block ----
            const int b = blk - ENCBLK0;
            int*   tokS = (int*)(sdyn + ENC_OFF);
            float* xs   = (float*)(sdyn + ENC_OFF + 256);
            float* hs   = (float*)(sdyn + ENC_OFF + 768);
            float* cs   = (float*)(sdyn + ENC_OFF + 896);
            float* egs  = (float*)(sdyn + ENC_OFF + 1024);
            if (tid < HID) { hs[tid] = 0.f; cs[tid] = 0.f; }
            if (tid < S_EN) tokS[tid] = en_batch[b * S_EN + tid];
            const int len = en_lens[b];
            const float bias = enc_bih[tid] + enc_bhh[tid];
            float wx[EMB_E], wh[HID];
#pragma unroll
            for (int k = 0; k < EMB_E; k++) wx[k] = enc_Wih[tid * EMB_E + k];
#pragma unroll
            for (int k = 0; k < HID; k++)   wh[k] = enc_Whh[tid * HID + k];
            bar_enc();
            if (tid < EMB_E) xs[tid] = en_emb[(size_t)tokS[0] * EMB_E + tid];
            bar_enc();
            for (int t = 0; t < len; t++) {
                const float* xcur = xs + (t & 1) * EMB_E;
                float xreg = 0.f;
                if (tid < EMB_E && t + 1 < len)
                    xreg = en_emb[(size_t)tokS[t + 1] * EMB_E + tid];
                float a0 = bias, a1 = 0.f, a2 = 0.f, a3 = 0.f;
#pragma unroll
                for (int k = 0; k < EMB_E; k += 4) {
                    a0 += wx[k] * xcur[k];         a1 += wx[k + 1] * xcur[k + 1];
                    a2 += wx[k + 2] * xcur[k + 2]; a3 += wx[k + 3] * xcur[k + 3];
                }
#pragma unroll
                for (int k = 0; k < HID; k += 4) {
                    a0 += wh[k] * hs[k];         a1 += wh[k + 1] * hs[k + 1];
                    a2 += wh[k + 2] * hs[k + 2]; a3 += wh[k + 3] * hs[k + 3];
                }
                egs[tid] = (a0 + a1) + (a2 + a3);
                bar_enc();
                if (tid < HID) {
                    float i_ = sigf(egs[tid]);
                    float f_ = sigf(egs[tid + 32]);
                    float gg = tanh_acc(egs[tid + 64]);
                    float o_ = sigf(egs[tid + 96]);
                    float cn = f_ * cs[tid] + i_ * gg;
                    cs[tid] = cn;
                    hs[tid] = o_ * tanh_acc(cn);
                }
                if (tid < EMB_E && t + 1 < len)
                    xs[((t + 1) & 1) * EMB_E + tid] = xreg;
                bar_enc();
            }
            if (tid < HID) {
                __stcg(&g_h[0][b][tid], hs[tid]);
                __stcg(&g_c[0][b][tid], cs[tid]);
            }
        }
        // upper 384 threads idle through phase A
    } else {
        // ---- zeroing blocks: g_amax, g_done, out[:,0,:] ----
        int z = (blk - ZBLK0) * NT + tid;              // 0..23551
        u64* am = (u64*)g_amax;
        for (int i = z; i < NSTEP * BB; i += 46 * NT) __stcg(&am[i], 0ull);
        unsigned* dn = (unsigned*)g_done;
        if (z < GROUPS * 64) __stcg(&dn[z], 0u);
        const int total4 = (BB * DE_V) / 4;            // 304000
        float4 zf = make_float4(0.f, 0.f, 0.f, 0.f);
        for (int j = z; j < total4; j += 46 * NT) {
            int e = j * 4;
            int b = e / DE_V;
            int r = e - b * DE_V;
            *(float4*)(out + (size_t)b * S_DE * DE_V + r) = zf;
        }
    }
    __syncthreads();   // phase-A smem dead

    // ---- staging: Whh (smem) + own fc_W row (registers) ----
    const int group = blk / CHUNKS;
    const int chunk = blk % CHUNKS;
    const int b0    = group * BPG;
    const int r0    = chunk * RPC;
    const int nrows = (r0 + RPC < DE_V) ? RPC : (DE_V - r0);
    const int mrows = (nrows < NT) ? nrows : NT;
    const int tailn = nrows - NT;                      // 2 for chunks 0..35, <0 last

    {
        u64* whh = (u64*)(sdyn + WHH_OFF);
        const u64* Wg = (const u64*)dec_Whh;
        for (int i = tid; i < 16 * G4; i += NT) {
            int k2 = i >> 7, g = i & 127;
            whh[i] = Wg[(size_t)g * 16 + k2];
        }
    }
    u64   wrow[16];
    float biasr = 0.f;
    const int myr = r0 + tid;
    const bool rowok = (tid < mrows);
    if (rowok) {
        const u64* src = (const u64*)(fc_W + (size_t)myr * HID);
#pragma unroll
        for (int j = 0; j < 16; j++) wrow[j] = src[j];
        biasr = __ldg(&fc_b[myr]);
    } else {
#pragma unroll
        for (int j = 0; j < 16; j++) wrow[j] = 0ull;
    }

    grid_sync();   // phase A + staging complete everywhere

    // ================= DECODE =================
    float (*hp)[HID] = (float(*)[HID])(sdyn + HP_OFF);
    float (*hn)[HID] = (float(*)[HID])(sdyn + HN_OFF);
    float (*gs)[G4]  = (float(*)[G4]) (sdyn + GS_OFF);
    int*  toks       = (int*)(sdyn + TOK_OFF);
    u64*  red_       = (u64*)(sdyn + RED_OFF);         // [16][512]
    const u64* whh_p = (const u64*)(sdyn + WHH_OFF);

    for (int step = 0; step < NSTEP; step++) {
        if (step) {
            if (tid == 0) {
                volatile unsigned* dp = &g_done[group][step - 1];
                while (*dp < CHUNKS) { }
                __threadfence();
            }
            __syncthreads();
        }
        const int rb = step & 1;
        const int wb = rb ^ 1;

        // --- tokens + previous h ---
        if (tid < BPG) {
            int b = b0 + tid;
            int tok;
            if (step == 0) tok = __ldg(&de_batch[b * S_DE]);
            else           tok = (int)(~(unsigned)__ldcg(&g_amax[step - 1][b]));
            toks[tid] = tok;
        }
        hp[tid >> 5][tid & 31] = __ldcg(&g_h[rb][b0 + (tid >> 5)][tid & 31]);
        __syncthreads();

        // --- gates: thread = (gate g, batch quartet q) ---
        {
            const int g = tid & 127, q = tid >> 7;
            u64 wreg[16];
#pragma unroll
            for (int k2 = 0; k2 < 16; k2++) wreg[k2] = whh_p[k2 * 128 + g];
#pragma unroll
            for (int bb = 0; bb < 4; bb++) {
                int bi = q * 4 + bb;
                const ulonglong2* h4 = (const ulonglong2*)hp[bi];
                u64 acc = 0ull;
#pragma unroll
                for (int k4 = 0; k4 < 8; k4++) {
                    ulonglong2 hv = h4[k4];
                    acc = fma2(wreg[2 * k4],     hv.x, acc);
                    acc = fma2(wreg[2 * k4 + 1], hv.y, acc);
                }
                gs[bi][g] = lo32(acc) + hi32(acc) + __ldg(&g_E[toks[bi]][g]);
            }
        }
        __syncthreads();

        // --- cell update: one (bi, j) per thread ---
        {
            int bi = tid >> 5, j = tid & 31;
            float i_ = sigf(gs[bi][j]);
            float f_ = sigf(gs[bi][j + 32]);
            float gg = tanh_acc(gs[bi][j + 64]);
            float o_ = sigf(gs[bi][j + 96]);
            float cp = __ldcg(&g_c[rb][b0 + bi][j]);
            float cn = f_ * cp + i_ * gg;
            float hv = o_ * tanh_acc(cn);
            hn[bi][j] = hv;
            if (chunk == 0) {
                __stcg(&g_h[wb][b0 + bi][j], hv);
                __stcg(&g_c[wb][b0 + bi][j], cn);
            }
        }
        __syncthreads();

        // --- FC: one register-resident row per thread, 16 batches.
        //     Packed argmax candidates go straight to smem (no p[] regs). ---
        const ulonglong2* h2 = (const ulonglong2*)hn;
        if (rowok) {
            u64 acc[BPG];
#pragma unroll
            for (int bi = 0; bi < BPG; bi++) acc[bi] = 0ull;
#pragma unroll
            for (int k4 = 0; k4 < 8; k4++) {
                u64 w0 = wrow[2 * k4], w1 = wrow[2 * k4 + 1];
#pragma unroll
                for (int bi = 0; bi < BPG; bi++) {
                    ulonglong2 hv = h2[bi * 8 + k4];   // broadcast LDS
                    acc[bi] = fma2(w0, hv.x, acc[bi]);
                    acc[bi] = fma2(w1, hv.y, acc[bi]);
                }
            }
            size_t obase = (size_t)(step + 1) * DE_V + myr;
#pragma unroll
            for (int bi = 0; bi < BPG; bi++) {
                float l = lo32(acc[bi]) + hi32(acc[bi]) + biasr;
                out[(size_t)(b0 + bi) * (S_DE * DE_V) + obase] = l;
                red_[bi * NT + tid] =
                    ((u64)key_of(l) << 32) | (unsigned)(~(unsigned)myr);
            }
        } else {
#pragma unroll
            for (int bi = 0; bi < BPG; bi++) red_[bi * NT + tid] = 0ull;
        }
        // tail rows (r0+512, r0+513) by threads 0..tailn-1 (weights L1-hot);
        // merge into own smem slot (same thread wrote it above — no race)
        if (tid < tailn) {
            int rt = r0 + NT + tid;
            const u64* wt = (const u64*)(fc_W + (size_t)rt * HID);
            u64 acc[BPG];
#pragma unroll
            for (int bi = 0; bi < BPG; bi++) acc[bi] = 0ull;
#pragma unroll
            for (int k4 = 0; k4 < 8; k4++) {
                u64 w0 = __ldg(&wt[2 * k4]), w1 = __ldg(&wt[2 * k4 + 1]);
#pragma unroll
                for (int bi = 0; bi < BPG; bi++) {
                    ulonglong2 hv = h2[bi * 8 + k4];
                    acc[bi] = fma2(w0, hv.x, acc[bi]);
                    acc[bi] = fma2(w1, hv.y, acc[bi]);
                }
            }
            float bt = __ldg(&fc_b[rt]);
            size_t obase = (size_t)(step + 1) * DE_V + rt;
#pragma unroll
            for (int bi = 0; bi < BPG; bi++) {
                float l = lo32(acc[bi]) + hi32(acc[bi]) + bt;
                out[(size_t)(b0 + bi) * (S_DE * DE_V) + obase] = l;
                u64 pt = ((u64)key_of(l) << 32) | (unsigned)(~(unsigned)rt);
                u64 cur = red_[bi * NT + tid];
                if (pt > cur) red_[bi * NT + tid] = pt;
            }
        }
        __syncthreads();

        // --- single-pass block argmax: warp w <-> batch w ---
        {
            int w = tid >> 5, lane = tid & 31;
            const u64* rw = red_ + w * NT;
            u64 m = rw[lane];
#pragma unroll
            for (int k = 1; k < 16; k++) {
                u64 v = rw[lane + 32 * k];
                if (v > m) m = v;
            }
#pragma unroll
            for (int off = 16; off; off >>= 1) {
                u64 v = __shfl_down_sync(0xffffffffu, m, off);
                if (v > m) m = v;
            }
            if (lane == 0) atomicMax(&g_amax[step][b0 + w], m);
        }

        // --- arrive ---
        __syncthreads();                   // all warps' atomicMax issued
        if (tid == 0) {
            __threadfence();
            atomicAdd(&g_done[group][step], 1u);
        }
    }
}

// ---------------- launch ----------------
extern "C" void kernel_launch(void* const* d_in, const int* in_sizes, int n_in,
                              void* d_out, int out_size) {
    const int*   en_batch = (const int*)d_in[0];
    const int*   en_lens  = (const int*)d_in[1];
    const int*   de_batch = (const int*)d_in[2];
    const float* en_emb   = (const float*)d_in[3];
    const float* enc_Wih  = (const float*)d_in[4];
    const float* enc_Whh  = (const float*)d_in[5];
    const float* enc_bih  = (const float*)d_in[6];
    const float* enc_bhh  = (const float*)d_in[7];
    const float* de_emb   = (const float*)d_in[8];
    const float* dec_Wih  = (const float*)d_in[9];
    const float* dec_Whh  = (const float*)d_in[10];
    const float* dec_bih  = (const float*)d_in[11];
    const float* dec_bhh  = (const float*)d_in[12];
    const float* fc_W     = (const float*)d_in[13];
    const float* fc_b     = (const float*)d_in[14];
    float* out = (float*)d_out;

    cudaFuncSetAttribute(seq2seq_kernel,
                         cudaFuncAttributeMaxDynamicSharedMemorySize, SMEM_TOTAL);
    seq2seq_kernel<<<NBLK, NT, SMEM_TOTAL>>>(
        en_batch, en_lens, de_batch, en_emb,
        enc_Wih, enc_Whh, enc_bih, enc_bhh,
        de_emb, dec_Wih, dec_bih, dec_bhh, dec_Whh,
        fc_W, fc_b, out);
}